// round 4
// baseline (speedup 1.0000x reference)
#include <cuda_runtime.h>
#include <math.h>

#define DIM 512
#define NF4 (DIM / 4)
#define TAU 0.1f
#define EPS_NORM 1e-12f
#define EPS_DENOM 1e-8f
#define MAX_POS 32768

__device__ double   g_neg_sum = 0.0;
__device__ unsigned g_done    = 0u;
__device__ float    g_pos_logit[MAX_POS];

__device__ __forceinline__ float block_reduce_sum(float v, float* part, int warps) {
    const int lane = threadIdx.x & 31;
    const int warp = threadIdx.x >> 5;
    #pragma unroll
    for (int o = 16; o > 0; o >>= 1) v += __shfl_xor_sync(0xffffffffu, v, o);
    if (lane == 0) part[warp] = v;
    __syncthreads();
    float r = 0.0f;
    for (int i = 0; i < warps; i++) r += part[i];
    __syncthreads();
    return r;
}

// ---------------------------------------------------------------------------
// Single fused kernel. Grid = [neg blocks | pos blocks | mix blocks].
// Streaming blocks: one warp per row; dot/||v||^2/||a||^2 in one pass with the
// RAW anchor read from global (L1-resident) -> zero prologue barriers.
// Last-block ticket does the finalize reduction.
// ---------------------------------------------------------------------------
template<int WARPS>
__global__ void __launch_bounds__(WARPS * 32) k_all(
    const float4* __restrict__ h,
    const float4* __restrict__ p,
    const float4* __restrict__ anchor4,
    const int*    __restrict__ mix_idx,
    const int*    __restrict__ idx_a,
    const int*    __restrict__ idx_b,
    const float*  __restrict__ alpha_raw,
    const float*  __restrict__ beta_raw,
    int nb_neg, int nb_pos,
    int n_hard, int n_pos, int n_mix,
    int total_blocks,
    float* __restrict__ out)
{
    __shared__ float  part[WARPS];
    __shared__ double dpart[WARPS];
    __shared__ bool   sh_last;
    __shared__ float  sh_S;

    const int tid  = threadIdx.x;
    const int warp = tid >> 5;
    const int lane = tid & 31;
    const int b    = blockIdx.x;

    if (b < nb_neg + nb_pos) {
        // ----- streaming path: no barriers before the loads -----
        const bool    is_neg = (b < nb_neg);
        const int     bb     = is_neg ? b : b - nb_neg;
        const int     nrows  = is_neg ? n_hard : n_pos;
        const float4* base   = is_neg ? h : p;
        const int     row    = bb * WARPS + warp;

        float val = 0.0f;
        if (row < nrows) {
            const float4* r = base + (size_t)row * NF4;
            float dot = 0.0f, ssv = 0.0f, ssa = 0.0f;
            #pragma unroll
            for (int i = 0; i < 4; i++) {
                float4 v = r[lane + 32 * i];
                float4 a = __ldg(&anchor4[lane + 32 * i]);
                dot += v.x * a.x + v.y * a.y + v.z * a.z + v.w * a.w;
                ssv += v.x * v.x + v.y * v.y + v.z * v.z + v.w * v.w;
                ssa += a.x * a.x + a.y * a.y + a.z * a.z + a.w * a.w;
            }
            #pragma unroll
            for (int o = 16; o > 0; o >>= 1) {
                dot += __shfl_xor_sync(0xffffffffu, dot, o);
                ssv += __shfl_xor_sync(0xffffffffu, ssv, o);
                ssa += __shfl_xor_sync(0xffffffffu, ssa, o);
            }
            if (lane == 0) {
                float l = dot / (fmaxf(sqrtf(ssa), EPS_NORM) *
                                 fmaxf(sqrtf(ssv), EPS_NORM) * TAU);
                if (is_neg) val = expf(l);
                else        g_pos_logit[row] = l;
            }
        }
        if (is_neg) {
            if (lane == 0) part[warp] = val;
            __syncthreads();
            if (tid == 0) {
                float s = 0.0f;
                #pragma unroll
                for (int i = 0; i < WARPS; i++) s += part[i];
                atomicAdd(&g_neg_sum, (double)s);
            }
        }
    } else {
        // ----- mix path: one synthesized negative per block -----
        const int j  = b - (nb_neg + nb_pos);          // 0 .. 2*n_mix-1
        const float* hs = (const float*)h;

        const bool active = (tid < NF4);
        float4 araw = active ? __ldg(&anchor4[tid])
                             : make_float4(0.f, 0.f, 0.f, 0.f);
        float ssa = block_reduce_sum(
            araw.x * araw.x + araw.y * araw.y + araw.z * araw.z + araw.w * araw.w,
            part, WARPS);
        float inv_na = 1.0f / fmaxf(sqrtf(ssa), EPS_NORM);
        float4 a = make_float4(araw.x * inv_na, araw.y * inv_na,
                               araw.z * inv_na, araw.w * inv_na);

        float4 v = make_float4(0.f, 0.f, 0.f, 0.f);

        if (j < n_mix) {
            // hardest = l2norm((1-alpha) * h_norm[m] + alpha * a_norm)
            int   m     = mix_idx[j];
            float alpha = alpha_raw[j] * 0.4f + 0.1f;
            float4 x = make_float4(0.f, 0.f, 0.f, 0.f);
            if (active) x = ((const float4*)(hs + (size_t)m * DIM))[tid];
            float ssx = block_reduce_sum(
                x.x * x.x + x.y * x.y + x.z * x.z + x.w * x.w, part, WARPS);
            float inv = (1.0f - alpha) / fmaxf(sqrtf(ssx), EPS_NORM);
            v.x = x.x * inv + alpha * a.x;
            v.y = x.y * inv + alpha * a.y;
            v.z = x.z * inv + alpha * a.z;
            v.w = x.w * inv + alpha * a.w;
        } else {
            // harder = l2norm(beta * h_norm[ia] + (1-beta) * h_norm[ib])
            int   jj   = j - n_mix;
            int   ia   = idx_a[jj];
            int   ib   = idx_b[jj];
            float beta = beta_raw[jj] * 0.4f + 0.3f;
            float4 xa = make_float4(0.f, 0.f, 0.f, 0.f);
            float4 xb = make_float4(0.f, 0.f, 0.f, 0.f);
            if (active) {
                xa = ((const float4*)(hs + (size_t)ia * DIM))[tid];
                xb = ((const float4*)(hs + (size_t)ib * DIM))[tid];
            }
            float ssaa = block_reduce_sum(
                xa.x * xa.x + xa.y * xa.y + xa.z * xa.z + xa.w * xa.w, part, WARPS);
            float ssbb = block_reduce_sum(
                xb.x * xb.x + xb.y * xb.y + xb.z * xb.z + xb.w * xb.w, part, WARPS);
            float inva = beta          / fmaxf(sqrtf(ssaa), EPS_NORM);
            float invb = (1.0f - beta) / fmaxf(sqrtf(ssbb), EPS_NORM);
            v.x = xa.x * inva + xb.x * invb;
            v.y = xa.y * inva + xb.y * invb;
            v.z = xa.z * inva + xb.z * invb;
            v.w = xa.w * inva + xb.w * invb;
        }

        float ssv = block_reduce_sum(
            v.x * v.x + v.y * v.y + v.z * v.z + v.w * v.w, part, WARPS);
        float dv = block_reduce_sum(
            v.x * a.x + v.y * a.y + v.z * a.z + v.w * a.w, part, WARPS);

        if (tid == 0) {
            float l = dv / (fmaxf(sqrtf(ssv), EPS_NORM) * TAU);
            atomicAdd(&g_neg_sum, (double)expf(l));
        }
    }

    // ---- ticket: last block to finish does the finalize ----
    __syncthreads();        // all warps' stores/atomics issued
    __threadfence();        // make them visible device-wide
    if (tid == 0)
        sh_last = (atomicAdd(&g_done, 1u) == (unsigned)(total_blocks - 1));
    __syncthreads();
    if (!sh_last) return;

    // ---- finalize (one block, WARPS*32 threads) ----
    if (tid == 0) sh_S = (float)atomicAdd(&g_neg_sum, 0.0) + EPS_DENOM;
    __syncthreads();
    const float S = sh_S;

    double acc = 0.0;
    for (int i = tid; i < n_pos; i += WARPS * 32) {
        float l = __ldcg(&g_pos_logit[i]);
        acc += (double)log1pf(S * expf(-l));
    }
    #pragma unroll
    for (int o = 16; o > 0; o >>= 1)
        acc += __shfl_xor_sync(0xffffffffu, acc, o);
    if (lane == 0) dpart[warp] = acc;
    __syncthreads();
    if (tid == 0) {
        double t = 0.0;
        #pragma unroll
        for (int i = 0; i < WARPS; i++) t += dpart[i];
        out[0] = (float)(t / (double)n_pos);
        // reset state for the next (graph-replayed) call
        g_neg_sum = 0.0;
        g_done    = 0u;
    }
}

extern "C" void kernel_launch(void* const* d_in, const int* in_sizes, int n_in,
                              void* d_out, int out_size) {
    const float* anchor    = (const float*)d_in[0];
    const float* positives = (const float*)d_in[1];
    const float* hardnegs  = (const float*)d_in[2];
    const int*   mix_idx   = (const int*)d_in[3];
    const int*   idx_a     = (const int*)d_in[4];
    const int*   idx_b     = (const int*)d_in[5];
    const float* alpha_raw = (const float*)d_in[6];
    const float* beta_raw  = (const float*)d_in[7];

    const int n_pos  = in_sizes[1] / DIM;
    const int n_hard = in_sizes[2] / DIM;
    const int n_mix  = in_sizes[3];

    constexpr int WARPS = 8;
    const int nb_neg = (n_hard + WARPS - 1) / WARPS;
    const int nb_pos = (n_pos  + WARPS - 1) / WARPS;
    const int grid   = nb_neg + nb_pos + 2 * n_mix;

    k_all<WARPS><<<grid, WARPS * 32>>>(
        (const float4*)hardnegs, (const float4*)positives,
        (const float4*)anchor,
        mix_idx, idx_a, idx_b, alpha_raw, beta_raw,
        nb_neg, nb_pos, n_hard, n_pos, n_mix,
        grid, (float*)d_out);
}

// round 5
// speedup vs baseline: 1.3081x; 1.3081x over previous
#include <cuda_runtime.h>
#include <math.h>

#define DIM 512
#define NF4 (DIM / 4)
#define TAU 0.1f
#define EPS_NORM 1e-12f
#define EPS_DENOM 1e-8f
#define MAX_POS 32768

__device__ double g_neg_sum = 0.0;
__device__ float  g_pos_logit[MAX_POS];

__device__ __forceinline__ float block_reduce_sum(float v, float* part, int warps) {
    const int lane = threadIdx.x & 31;
    const int warp = threadIdx.x >> 5;
    #pragma unroll
    for (int o = 16; o > 0; o >>= 1) v += __shfl_xor_sync(0xffffffffu, v, o);
    if (lane == 0) part[warp] = v;
    __syncthreads();
    float r = 0.0f;
    for (int i = 0; i < warps; i++) r += part[i];
    __syncthreads();
    return r;
}

// ---------------------------------------------------------------------------
// k_main: grid = [neg blocks | pos blocks | mix blocks], 256 threads.
// Prologue: raw anchor -> shared, one block-reduce for ||a||^2.
// Streaming: one warp per row, dot + ||v||^2 in one pass (anchor from smem),
// inv_na folded into the scalar logit. No fences, no tickets.
// ---------------------------------------------------------------------------
template<int WARPS>
__global__ void __launch_bounds__(WARPS * 32) k_main(
    const float4* __restrict__ h,
    const float4* __restrict__ p,
    const float4* __restrict__ anchor4,
    const int*    __restrict__ mix_idx,
    const int*    __restrict__ idx_a,
    const int*    __restrict__ idx_b,
    const float*  __restrict__ alpha_raw,
    const float*  __restrict__ beta_raw,
    int nb_neg, int nb_pos,
    int n_hard, int n_pos, int n_mix)
{
    __shared__ float4 sav[NF4];     // RAW anchor (2 KB)
    __shared__ float  part[WARPS];
    __shared__ float  sh_invna;

    const int tid  = threadIdx.x;
    const int warp = tid >> 5;
    const int lane = tid & 31;
    const int b    = blockIdx.x;

    // ---- prologue: anchor to shared + ||a||^2 (cheap, measured in R3/R4) ----
    {
        float4 av = make_float4(0.f, 0.f, 0.f, 0.f);
        float  ss = 0.0f;
        if (tid < NF4) {
            av = __ldg(&anchor4[tid]);
            sav[tid] = av;
            ss = av.x * av.x + av.y * av.y + av.z * av.z + av.w * av.w;
        }
        ss = block_reduce_sum(ss, part, WARPS);
        if (tid == 0) sh_invna = 1.0f / fmaxf(sqrtf(ss), EPS_NORM);
        __syncthreads();
    }
    const float inv_na = sh_invna;

    if (b < nb_neg + nb_pos) {
        // ----- streaming path -----
        const bool    is_neg = (b < nb_neg);
        const int     bb     = is_neg ? b : b - nb_neg;
        const int     nrows  = is_neg ? n_hard : n_pos;
        const float4* base   = is_neg ? h : p;
        const int     row    = bb * WARPS + warp;

        float val = 0.0f;
        if (row < nrows) {
            const float4* r = base + (size_t)row * NF4;
            float dot = 0.0f, ssv = 0.0f;
            #pragma unroll
            for (int i = 0; i < 4; i++) {
                float4 v = __ldcs(&r[lane + 32 * i]);   // read-once: evict-first
                float4 a = sav[lane + 32 * i];
                dot += v.x * a.x + v.y * a.y + v.z * a.z + v.w * a.w;
                ssv += v.x * v.x + v.y * v.y + v.z * v.z + v.w * v.w;
            }
            #pragma unroll
            for (int o = 16; o > 0; o >>= 1) {
                dot += __shfl_xor_sync(0xffffffffu, dot, o);
                ssv += __shfl_xor_sync(0xffffffffu, ssv, o);
            }
            if (lane == 0) {
                float l = dot * inv_na /
                          (fmaxf(sqrtf(ssv), EPS_NORM) * TAU);
                if (is_neg) val = expf(l);
                else        g_pos_logit[row] = l;
            }
        }
        if (is_neg) {
            if (lane == 0) part[warp] = val;
            __syncthreads();
            if (tid == 0) {
                float s = 0.0f;
                #pragma unroll
                for (int i = 0; i < WARPS; i++) s += part[i];
                atomicAdd(&g_neg_sum, (double)s);
            }
        }
        return;
    }

    // ----- mix path: one synthesized negative per block -----
    const int j  = b - (nb_neg + nb_pos);          // 0 .. 2*n_mix-1
    const float* hs = (const float*)h;

    const bool active = (tid < NF4);
    float4 a = make_float4(0.f, 0.f, 0.f, 0.f);
    if (active) {
        float4 ar = sav[tid];
        a = make_float4(ar.x * inv_na, ar.y * inv_na, ar.z * inv_na, ar.w * inv_na);
    }
    float4 v = make_float4(0.f, 0.f, 0.f, 0.f);

    if (j < n_mix) {
        // hardest = l2norm((1-alpha) * h_norm[m] + alpha * a_norm)
        int   m     = mix_idx[j];
        float alpha = alpha_raw[j] * 0.4f + 0.1f;
        float4 x = make_float4(0.f, 0.f, 0.f, 0.f);
        if (active) x = ((const float4*)(hs + (size_t)m * DIM))[tid];
        float ssx = block_reduce_sum(
            x.x * x.x + x.y * x.y + x.z * x.z + x.w * x.w, part, WARPS);
        float inv = (1.0f - alpha) / fmaxf(sqrtf(ssx), EPS_NORM);
        v.x = x.x * inv + alpha * a.x;
        v.y = x.y * inv + alpha * a.y;
        v.z = x.z * inv + alpha * a.z;
        v.w = x.w * inv + alpha * a.w;
    } else {
        // harder = l2norm(beta * h_norm[ia] + (1-beta) * h_norm[ib])
        int   jj   = j - n_mix;
        int   ia   = idx_a[jj];
        int   ib   = idx_b[jj];
        float beta = beta_raw[jj] * 0.4f + 0.3f;
        float4 xa = make_float4(0.f, 0.f, 0.f, 0.f);
        float4 xb = make_float4(0.f, 0.f, 0.f, 0.f);
        if (active) {
            xa = ((const float4*)(hs + (size_t)ia * DIM))[tid];
            xb = ((const float4*)(hs + (size_t)ib * DIM))[tid];
        }
        float ssaa = block_reduce_sum(
            xa.x * xa.x + xa.y * xa.y + xa.z * xa.z + xa.w * xa.w, part, WARPS);
        float ssbb = block_reduce_sum(
            xb.x * xb.x + xb.y * xb.y + xb.z * xb.z + xb.w * xb.w, part, WARPS);
        float inva = beta          / fmaxf(sqrtf(ssaa), EPS_NORM);
        float invb = (1.0f - beta) / fmaxf(sqrtf(ssbb), EPS_NORM);
        v.x = xa.x * inva + xb.x * invb;
        v.y = xa.y * inva + xb.y * invb;
        v.z = xa.z * inva + xb.z * invb;
        v.w = xa.w * inva + xb.w * invb;
    }

    float ssv = block_reduce_sum(
        v.x * v.x + v.y * v.y + v.z * v.z + v.w * v.w, part, WARPS);
    float dv = block_reduce_sum(
        v.x * a.x + v.y * a.y + v.z * a.z + v.w * a.w, part, WARPS);

    if (tid == 0) {
        float l = dv / (fmaxf(sqrtf(ssv), EPS_NORM) * TAU);
        atomicAdd(&g_neg_sum, (double)expf(l));
    }
}

// ---------------------------------------------------------------------------
// k_final: one block, 1024 threads. loss = mean log1p((S+eps) * exp(-l)).
// Resets g_neg_sum for the next graph replay.
// ---------------------------------------------------------------------------
__global__ void k_final(float* __restrict__ out, int n_pos) {
    __shared__ double red[32];
    const int tid = threadIdx.x;
    const float S = (float)g_neg_sum + EPS_DENOM;

    double acc = 0.0;
    for (int i = tid; i < n_pos; i += blockDim.x) {
        float l = g_pos_logit[i];
        acc += (double)log1pf(S * expf(-l));
    }
    #pragma unroll
    for (int o = 16; o > 0; o >>= 1)
        acc += __shfl_xor_sync(0xffffffffu, acc, o);
    if ((tid & 31) == 0) red[tid >> 5] = acc;
    __syncthreads();
    if (tid < 32) {
        double v = (tid < (blockDim.x >> 5)) ? red[tid] : 0.0;
        #pragma unroll
        for (int o = 16; o > 0; o >>= 1)
            v += __shfl_xor_sync(0xffffffffu, v, o);
        if (tid == 0) {
            out[0] = (float)(v / (double)n_pos);
            g_neg_sum = 0.0;   // reset for next replay
        }
    }
}

extern "C" void kernel_launch(void* const* d_in, const int* in_sizes, int n_in,
                              void* d_out, int out_size) {
    const float* anchor    = (const float*)d_in[0];
    const float* positives = (const float*)d_in[1];
    const float* hardnegs  = (const float*)d_in[2];
    const int*   mix_idx   = (const int*)d_in[3];
    const int*   idx_a     = (const int*)d_in[4];
    const int*   idx_b     = (const int*)d_in[5];
    const float* alpha_raw = (const float*)d_in[6];
    const float* beta_raw  = (const float*)d_in[7];

    const int n_pos  = in_sizes[1] / DIM;
    const int n_hard = in_sizes[2] / DIM;
    const int n_mix  = in_sizes[3];

    constexpr int WARPS = 8;
    const int nb_neg = (n_hard + WARPS - 1) / WARPS;
    const int nb_pos = (n_pos  + WARPS - 1) / WARPS;
    const int grid   = nb_neg + nb_pos + 2 * n_mix;

    k_main<WARPS><<<grid, WARPS * 32>>>(
        (const float4*)hardnegs, (const float4*)positives,
        (const float4*)anchor,
        mix_idx, idx_a, idx_b, alpha_raw, beta_raw,
        nb_neg, nb_pos, n_hard, n_pos, n_mix);
    k_final<<<1, 1024>>>((float*)d_out, n_pos);
}

// round 6
// speedup vs baseline: 1.5732x; 1.2027x over previous
#include <cuda_runtime.h>
#include <math.h>

#define DIM 512
#define NF4 (DIM / 4)
#define TAU 0.1f
#define EPS_NORM 1e-12f
#define EPS_DENOM 1e-8f
#define MAX_POS 32768

__device__ double g_neg_sum = 0.0;
__device__ double g_pos_sum = 0.0;
__device__ float  g_pos_logit[MAX_POS];

__device__ __forceinline__ float block_reduce_sum(float v, float* part, int warps) {
    const int lane = threadIdx.x & 31;
    const int warp = threadIdx.x >> 5;
    #pragma unroll
    for (int o = 16; o > 0; o >>= 1) v += __shfl_xor_sync(0xffffffffu, v, o);
    if (lane == 0) part[warp] = v;
    __syncthreads();
    float r = 0.0f;
    for (int i = 0; i < warps; i++) r += part[i];
    __syncthreads();
    return r;
}

// ---------------------------------------------------------------------------
// k_main: grid = [neg blocks | pos blocks | mix blocks], 256 threads.
// (Unchanged from R5 — measured ~24-25us, near the 23us traffic floor.)
// ---------------------------------------------------------------------------
template<int WARPS>
__global__ void __launch_bounds__(WARPS * 32) k_main(
    const float4* __restrict__ h,
    const float4* __restrict__ p,
    const float4* __restrict__ anchor4,
    const int*    __restrict__ mix_idx,
    const int*    __restrict__ idx_a,
    const int*    __restrict__ idx_b,
    const float*  __restrict__ alpha_raw,
    const float*  __restrict__ beta_raw,
    int nb_neg, int nb_pos,
    int n_hard, int n_pos, int n_mix)
{
    __shared__ float4 sav[NF4];     // RAW anchor (2 KB)
    __shared__ float  part[WARPS];
    __shared__ float  sh_invna;

    const int tid  = threadIdx.x;
    const int warp = tid >> 5;
    const int lane = tid & 31;
    const int b    = blockIdx.x;

    // ---- prologue: anchor to shared + ||a||^2 ----
    {
        float4 av = make_float4(0.f, 0.f, 0.f, 0.f);
        float  ss = 0.0f;
        if (tid < NF4) {
            av = __ldg(&anchor4[tid]);
            sav[tid] = av;
            ss = av.x * av.x + av.y * av.y + av.z * av.z + av.w * av.w;
        }
        ss = block_reduce_sum(ss, part, WARPS);
        if (tid == 0) sh_invna = 1.0f / fmaxf(sqrtf(ss), EPS_NORM);
        __syncthreads();
    }
    const float inv_na = sh_invna;

    if (b < nb_neg + nb_pos) {
        // ----- streaming path -----
        const bool    is_neg = (b < nb_neg);
        const int     bb     = is_neg ? b : b - nb_neg;
        const int     nrows  = is_neg ? n_hard : n_pos;
        const float4* base   = is_neg ? h : p;
        const int     row    = bb * WARPS + warp;

        float val = 0.0f;
        if (row < nrows) {
            const float4* r = base + (size_t)row * NF4;
            float dot = 0.0f, ssv = 0.0f;
            #pragma unroll
            for (int i = 0; i < 4; i++) {
                float4 v = __ldcs(&r[lane + 32 * i]);   // read-once: evict-first
                float4 a = sav[lane + 32 * i];
                dot += v.x * a.x + v.y * a.y + v.z * a.z + v.w * a.w;
                ssv += v.x * v.x + v.y * v.y + v.z * v.z + v.w * v.w;
            }
            #pragma unroll
            for (int o = 16; o > 0; o >>= 1) {
                dot += __shfl_xor_sync(0xffffffffu, dot, o);
                ssv += __shfl_xor_sync(0xffffffffu, ssv, o);
            }
            if (lane == 0) {
                float l = dot * inv_na /
                          (fmaxf(sqrtf(ssv), EPS_NORM) * TAU);
                if (is_neg) val = expf(l);
                else        g_pos_logit[row] = l;
            }
        }
        if (is_neg) {
            if (lane == 0) part[warp] = val;
            __syncthreads();
            if (tid == 0) {
                float s = 0.0f;
                #pragma unroll
                for (int i = 0; i < WARPS; i++) s += part[i];
                atomicAdd(&g_neg_sum, (double)s);
            }
        }
        return;
    }

    // ----- mix path: one synthesized negative per block -----
    const int j  = b - (nb_neg + nb_pos);          // 0 .. 2*n_mix-1
    const float* hs = (const float*)h;

    const bool active = (tid < NF4);
    float4 a = make_float4(0.f, 0.f, 0.f, 0.f);
    if (active) {
        float4 ar = sav[tid];
        a = make_float4(ar.x * inv_na, ar.y * inv_na, ar.z * inv_na, ar.w * inv_na);
    }
    float4 v = make_float4(0.f, 0.f, 0.f, 0.f);

    if (j < n_mix) {
        // hardest = l2norm((1-alpha) * h_norm[m] + alpha * a_norm)
        int   m     = mix_idx[j];
        float alpha = alpha_raw[j] * 0.4f + 0.1f;
        float4 x = make_float4(0.f, 0.f, 0.f, 0.f);
        if (active) x = ((const float4*)(hs + (size_t)m * DIM))[tid];
        float ssx = block_reduce_sum(
            x.x * x.x + x.y * x.y + x.z * x.z + x.w * x.w, part, WARPS);
        float inv = (1.0f - alpha) / fmaxf(sqrtf(ssx), EPS_NORM);
        v.x = x.x * inv + alpha * a.x;
        v.y = x.y * inv + alpha * a.y;
        v.z = x.z * inv + alpha * a.z;
        v.w = x.w * inv + alpha * a.w;
    } else {
        // harder = l2norm(beta * h_norm[ia] + (1-beta) * h_norm[ib])
        int   jj   = j - n_mix;
        int   ia   = idx_a[jj];
        int   ib   = idx_b[jj];
        float beta = beta_raw[jj] * 0.4f + 0.3f;
        float4 xa = make_float4(0.f, 0.f, 0.f, 0.f);
        float4 xb = make_float4(0.f, 0.f, 0.f, 0.f);
        if (active) {
            xa = ((const float4*)(hs + (size_t)ia * DIM))[tid];
            xb = ((const float4*)(hs + (size_t)ib * DIM))[tid];
        }
        float ssaa = block_reduce_sum(
            xa.x * xa.x + xa.y * xa.y + xa.z * xa.z + xa.w * xa.w, part, WARPS);
        float ssbb = block_reduce_sum(
            xb.x * xb.x + xb.y * xb.y + xb.z * xb.z + xb.w * xb.w, part, WARPS);
        float inva = beta          / fmaxf(sqrtf(ssaa), EPS_NORM);
        float invb = (1.0f - beta) / fmaxf(sqrtf(ssbb), EPS_NORM);
        v.x = xa.x * inva + xb.x * invb;
        v.y = xa.y * inva + xb.y * invb;
        v.z = xa.z * inva + xb.z * invb;
        v.w = xa.w * inva + xb.w * invb;
    }

    float ssv = block_reduce_sum(
        v.x * v.x + v.y * v.y + v.z * v.z + v.w * v.w, part, WARPS);
    float dv = block_reduce_sum(
        v.x * a.x + v.y * a.y + v.z * a.z + v.w * a.w, part, WARPS);

    if (tid == 0) {
        float l = dv / (fmaxf(sqrtf(ssv), EPS_NORM) * TAU);
        atomicAdd(&g_neg_sum, (double)expf(l));
    }
}

// ---------------------------------------------------------------------------
// k_pos_reduce: many blocks, one logit per thread. Block partial (double) ->
// one atomicAdd per block into g_pos_sum.
// ---------------------------------------------------------------------------
__global__ void __launch_bounds__(256) k_pos_reduce(int n_pos) {
    __shared__ double red[8];
    __shared__ float  sh_S;
    const int tid = threadIdx.x;
    const int i   = blockIdx.x * 256 + tid;

    if (tid == 0) sh_S = (float)g_neg_sum + EPS_DENOM;
    __syncthreads();
    const float S = sh_S;

    double acc = 0.0;
    if (i < n_pos) {
        float l = g_pos_logit[i];
        acc = (double)log1pf(S * expf(-l));
    }
    #pragma unroll
    for (int o = 16; o > 0; o >>= 1)
        acc += __shfl_xor_sync(0xffffffffu, acc, o);
    if ((tid & 31) == 0) red[tid >> 5] = acc;
    __syncthreads();
    if (tid == 0) {
        double s = 0.0;
        #pragma unroll
        for (int k = 0; k < 8; k++) s += red[k];
        atomicAdd(&g_pos_sum, s);
    }
}

// ---------------------------------------------------------------------------
// k_write: one thread. Writes loss; resets accumulators for next replay.
// ---------------------------------------------------------------------------
__global__ void k_write(float* __restrict__ out, double inv_npos) {
    out[0] = (float)(g_pos_sum * inv_npos);
    g_pos_sum = 0.0;
    g_neg_sum = 0.0;
}

extern "C" void kernel_launch(void* const* d_in, const int* in_sizes, int n_in,
                              void* d_out, int out_size) {
    const float* anchor    = (const float*)d_in[0];
    const float* positives = (const float*)d_in[1];
    const float* hardnegs  = (const float*)d_in[2];
    const int*   mix_idx   = (const int*)d_in[3];
    const int*   idx_a     = (const int*)d_in[4];
    const int*   idx_b     = (const int*)d_in[5];
    const float* alpha_raw = (const float*)d_in[6];
    const float* beta_raw  = (const float*)d_in[7];

    const int n_pos  = in_sizes[1] / DIM;
    const int n_hard = in_sizes[2] / DIM;
    const int n_mix  = in_sizes[3];

    constexpr int WARPS = 8;
    const int nb_neg = (n_hard + WARPS - 1) / WARPS;
    const int nb_pos = (n_pos  + WARPS - 1) / WARPS;
    const int grid   = nb_neg + nb_pos + 2 * n_mix;

    k_main<WARPS><<<grid, WARPS * 32>>>(
        (const float4*)hardnegs, (const float4*)positives,
        (const float4*)anchor,
        mix_idx, idx_a, idx_b, alpha_raw, beta_raw,
        nb_neg, nb_pos, n_hard, n_pos, n_mix);
    k_pos_reduce<<<(n_pos + 255) / 256, 256>>>(n_pos);
    k_write<<<1, 1>>>((float*)d_out, 1.0 / (double)n_pos);
}